// round 7
// baseline (speedup 1.0000x reference)
#include <cuda_runtime.h>
#include <cuda_fp16.h>
#include <cstdint>

#define T_TOK   32768
#define IN_DIM  2048
#define OUT_DIM 768
#define NEXP    64
#define RRANK   16
#define SCALING 2.0f

#define BM 128
#define BN 128
#define BK 32
#define KT3 (IN_DIM / BK)                  /* 64 stages */
#define MAX_MTILES 320
#define NT 6
#define NTHREADS 128                       /* 4 warps, 2m x 2n, warp tile 64x64 */

// smem row strides (bytes), conflict-free for ldmatrix (stride/16 odd)
#define SA  80    /* A: 32 halves + pad;  5r mod 8 distinct  */
#define SB  272   /* B: 128 halves + pad; 17k mod 8 distinct */
#define SWA 48    /* WA: 16 halves + pad; 3k mod 8 distinct  */

#define A_STG  (128 * SA)   /* 10240 */
#define B_STG  (32 * SB)    /* 8704  */
#define WA_STG (32 * SWA)   /* 1536  */

#define SM_A   0
#define SM_B   (4 * A_STG)                 /* 40960: 2-stage fp16 B */
#define SM_WA  (SM_B + 2 * B_STG)          /* 58368 */
#define SM_MSZ (SM_WA + 4 * WA_STG)        /* 64512 */
#define SMEM_BYTES (SM_MSZ + 256)          /* 64768 -> 2 CTAs/SM easily */

// fp16 scratch (x / w_a / w_b only; w_base converted in-kernel)
__device__ __align__(16) __half g_xh [(size_t)T_TOK * IN_DIM];
__device__ __align__(16) __half g_wah[(size_t)NEXP * IN_DIM * RRANK];
__device__ __align__(16) __half g_wsh[(size_t)NEXP * RRANK * OUT_DIM];

__device__ __forceinline__ uint32_t h2u(__half2 h) {
    return *reinterpret_cast<uint32_t*>(&h);
}

__device__ __forceinline__ void cp16(uint32_t dst, const void* src, bool valid) {
    int sz = valid ? 16 : 0;   // sz=0 zero-fills, reads nothing
    asm volatile("cp.async.cg.shared.global [%0], [%1], 16, %2;\n"
                 :: "r"(dst), "l"(src), "r"(sz));
}

__device__ __forceinline__ void ldsm_x4(uint32_t* r, uint32_t addr) {
    asm volatile("ldmatrix.sync.aligned.m8n8.x4.shared.b16 {%0,%1,%2,%3}, [%4];"
                 : "=r"(r[0]), "=r"(r[1]), "=r"(r[2]), "=r"(r[3]) : "r"(addr));
}
__device__ __forceinline__ void ldsm_x4_t(uint32_t* r, uint32_t addr) {
    asm volatile("ldmatrix.sync.aligned.m8n8.x4.trans.shared.b16 {%0,%1,%2,%3}, [%4];"
                 : "=r"(r[0]), "=r"(r[1]), "=r"(r[2]), "=r"(r[3]) : "r"(addr));
}
__device__ __forceinline__ void ldsm_x2_t(uint32_t* r, uint32_t addr) {
    asm volatile("ldmatrix.sync.aligned.m8n8.x2.trans.shared.b16 {%0,%1}, [%2];"
                 : "=r"(r[0]), "=r"(r[1]) : "r"(addr));
}

__device__ __forceinline__ void mma_f16(float* c, const uint32_t* a,
                                        uint32_t b0, uint32_t b1) {
    asm volatile(
        "mma.sync.aligned.m16n8k16.row.col.f32.f16.f16.f32 "
        "{%0,%1,%2,%3},{%4,%5,%6,%7},{%8,%9},{%0,%1,%2,%3};"
        : "+f"(c[0]), "+f"(c[1]), "+f"(c[2]), "+f"(c[3])
        : "r"(a[0]), "r"(a[1]), "r"(a[2]), "r"(a[3]), "r"(b0), "r"(b1));
}

// ---- prepass: fp32 -> fp16, vectorized grid-stride ----
__global__ void __launch_bounds__(256)
cvt_kernel(const float4* __restrict__ src, uint2* __restrict__ dst, int n4) {
    int stride = gridDim.x * blockDim.x;
    for (int i = blockIdx.x * blockDim.x + threadIdx.x; i < n4; i += stride) {
        float4 f = src[i];
        uint2 u;
        u.x = h2u(__floats2half2_rn(f.x, f.y));
        u.y = h2u(__floats2half2_rn(f.z, f.w));
        dst[i] = u;
    }
}

__global__ __launch_bounds__(NTHREADS, 2)
void lora_moe_h4(const int*   __restrict__ m_sizes,
                 const float* __restrict__ w_base,
                 float*       __restrict__ out) {
    extern __shared__ __align__(128) char smem[];
    const uint32_t sb = (uint32_t)__cvta_generic_to_shared(smem);

    const int tid  = threadIdx.x;
    const int lane = tid & 31;
    const int warp = tid >> 5;
    const int wm   = warp & 1;   // m half (64 rows)
    const int wn   = warp >> 1;  // n half (64 cols)

    int* msz = (int*)(smem + SM_MSZ);
    if (tid < NEXP) msz[tid] = m_sizes[tid];
    __syncthreads();

    // ---- tile scan (m-tile = blockIdx.y) ----
    int e = 0, row_start = 0, m_len = 0, found = 0;
    {
        const int mt = blockIdx.y;
        int acc_rows = 0, acc_tiles = 0;
        for (e = 0; e < NEXP; e++) {
            int m  = msz[e];
            int nt = (m + BM - 1) >> 7;
            if (mt < acc_tiles + nt) {
                int lt    = mt - acc_tiles;
                row_start = acc_rows + lt * BM;
                m_len     = min(BM, m - lt * BM);
                found     = 1;
                break;
            }
            acc_tiles += nt;
            acc_rows  += m;
        }
    }
    if (!found) return;

    const int n0 = blockIdx.x * BN;
    const __half* xg   = g_xh  + (size_t)row_start * IN_DIM;
    const float*  bg32 = w_base + (size_t)e * IN_DIM * OUT_DIM + n0;
    const __half* ag   = g_wah + (size_t)e * IN_DIM * RRANK;
    const __half* wbg  = g_wsh + (size_t)e * RRANK  * OUT_DIM + n0;

    float acc[4][8][4];    // 4 m-frags x 8 n-frags
    float aacc[4][4];
    #pragma unroll
    for (int i = 0; i < 4; i++) {
        #pragma unroll
        for (int j = 0; j < 8; j++)
            #pragma unroll
            for (int q = 0; q < 4; q++) acc[i][j][q] = 0.f;
        #pragma unroll
        for (int q = 0; q < 4; q++) aacc[i][q] = 0.f;
    }

    // ---- A / WA async loader (fp16 srcs), 4-stage ring ----
    auto load_A = [&](int kt) {
        const int st = kt & 3;
        const uint32_t A  = sb + SM_A  + st * A_STG;
        const uint32_t WA = sb + SM_WA + st * WA_STG;
        const int k0 = kt * BK;
        #pragma unroll
        for (int j = 0; j < 4; j++) {
            int idx = tid + j * NTHREADS;
            int row = idx >> 2, kc = idx & 3;
            bool v = (row_start + row) < T_TOK;
            cp16(A + row * SA + kc * 16, xg + (size_t)row * IN_DIM + k0 + kc * 8, v);
        }
        if (tid < 64) {
            int k = tid >> 1, rq = tid & 1;
            cp16(WA + k * SWA + rq * 16, ag + (size_t)(k0 + k) * RRANK + rq * 8, true);
        }
        asm volatile("cp.async.commit_group;\n");
    };

    // ---- B fp32 register staging: 8 x float4 per thread per stage ----
    float4 fb[8];
    auto load_Bregs = [&](int kt) {
        const int k0 = kt * BK;
        #pragma unroll
        for (int j = 0; j < 8; j++) {
            int idx = tid + j * NTHREADS;          // 0..1023
            int k = idx >> 5, c4 = idx & 31;       // row k (0..31), 16B chunk c4
            fb[j] = *(const float4*)(bg32 + (size_t)(k0 + k) * OUT_DIM + c4 * 4);
        }
    };
    auto sts_B = [&](int kt) {
        const uint32_t B = sb + SM_B + (kt & 1) * B_STG;
        #pragma unroll
        for (int j = 0; j < 8; j++) {
            int idx = tid + j * NTHREADS;
            int k = idx >> 5, c4 = idx & 31;
            uint2 u;
            u.x = h2u(__floats2half2_rn(fb[j].x, fb[j].y));
            u.y = h2u(__floats2half2_rn(fb[j].z, fb[j].w));
            *(uint2*)(smem + 0 + (B - sb) + k * SB + c4 * 8) = u;
        }
    };

    // per-lane ldmatrix base offsets
    const uint32_t a_off  = (uint32_t)((wm * 64 + (lane & 15)) * SA + (lane >> 4) * 16);
    const uint32_t b_off  = (uint32_t)((lane & 15) * SB + (wn * 64 + (lane >> 4) * 8) * 2);
    const uint32_t wa_off = (uint32_t)((lane & 15) * SWA + wn * 16);

    auto compute = [&](int kt) {
        const int st = kt & 3;
        const uint32_t Ab = sb + SM_A  + st * A_STG  + a_off;
        const uint32_t Bb = sb + SM_B  + (kt & 1) * B_STG + b_off;
        const uint32_t Wb = sb + SM_WA + st * WA_STG + wa_off;
        #pragma unroll
        for (int ks = 0; ks < 2; ks++) {   // 2 x K=16
            uint32_t am[4][4];
            #pragma unroll
            for (int mf = 0; mf < 4; mf++)
                ldsm_x4(am[mf], Ab + mf * 16 * SA + ks * 32);
            uint32_t wf[2];
            ldsm_x2_t(wf, Wb + ks * 16 * SWA);
            #pragma unroll
            for (int p = 0; p < 4; p++) {
                uint32_t bf[4];
                ldsm_x4_t(bf, Bb + ks * 16 * SB + p * 32);
                #pragma unroll
                for (int mf = 0; mf < 4; mf++) {
                    mma_f16(acc[mf][2 * p],     am[mf], bf[0], bf[1]);
                    mma_f16(acc[mf][2 * p + 1], am[mf], bf[2], bf[3]);
                }
            }
            #pragma unroll
            for (int mf = 0; mf < 4; mf++)
                mma_f16(aacc[mf], am[mf], wf[0], wf[1]);
        }
    };

    // ---- pipeline: A 4-stage cp.async, B 2-stage via registers ----
    load_Bregs(0);
    load_A(0);
    load_A(1);
    load_A(2);
    sts_B(0);
    #pragma unroll 1
    for (int kt = 0; kt < KT3; kt++) {
        if (kt < KT3 - 2)       asm volatile("cp.async.wait_group 2;\n");
        else if (kt == KT3 - 2) asm volatile("cp.async.wait_group 1;\n");
        else                    asm volatile("cp.async.wait_group 0;\n");
        __syncthreads();                       // A(kt) + B16(kt) visible
        if (kt + 1 < KT3) load_Bregs(kt + 1);  // LDG in flight under mma
        if (kt + 3 < KT3) load_A(kt + 3);
        compute(kt);
        __syncthreads();                       // readers of B16(kt^1) done
        if (kt + 1 < KT3) sts_B(kt + 1);
    }
    __syncthreads();

    // ---- LoRA epilogue: a*SCALING -> A stage0 (fp16), w_b -> B buf0, K=16 mma ----
    {
        char* Asc = smem + SM_A;
        const int row0 = wm * 64 + (lane >> 2);
        const int cb   = wn * 8 + 2 * (lane & 3);
        #pragma unroll
        for (int mf = 0; mf < 4; mf++) {
            int r = row0 + mf * 16;
            *(uint32_t*)(Asc + r * SA + cb * 2) =
                h2u(__floats2half2_rn(aacc[mf][0] * SCALING, aacc[mf][1] * SCALING));
            *(uint32_t*)(Asc + (r + 8) * SA + cb * 2) =
                h2u(__floats2half2_rn(aacc[mf][2] * SCALING, aacc[mf][3] * SCALING));
        }
    }
    {
        char* Wbs = smem + SM_B;
        #pragma unroll
        for (int j = 0; j < 2; j++) {
            int idx = tid + j * NTHREADS;       // 0..255
            int k = idx >> 4, nq = idx & 15;
            uint4 v = *(const uint4*)(wbg + (size_t)k * OUT_DIM + nq * 8);
            *(uint4*)(Wbs + k * SB + nq * 16) = v;
        }
    }
    __syncthreads();

    {
        const int row = wm * 64 + (lane >> 2);
        uint32_t am[4][4];
        #pragma unroll
        for (int mf = 0; mf < 4; mf++) {
            const uint32_t base = sb + SM_A + (row + mf * 16) * SA + (lane & 3) * 4;
            asm volatile("ld.shared.b32 %0, [%1];" : "=r"(am[mf][0]) : "r"(base));
            asm volatile("ld.shared.b32 %0, [%1];" : "=r"(am[mf][1]) : "r"(base + 8 * SA));
            asm volatile("ld.shared.b32 %0, [%1];" : "=r"(am[mf][2]) : "r"(base + 16));
            asm volatile("ld.shared.b32 %0, [%1];" : "=r"(am[mf][3]) : "r"(base + 8 * SA + 16));
        }
        const uint32_t Bb = sb + SM_B + b_off;
        #pragma unroll
        for (int p = 0; p < 4; p++) {
            uint32_t bf[4];
            ldsm_x4_t(bf, Bb + p * 32);
            #pragma unroll
            for (int mf = 0; mf < 4; mf++) {
                mma_f16(acc[mf][2 * p],     am[mf], bf[0], bf[1]);
                mma_f16(acc[mf][2 * p + 1], am[mf], bf[2], bf[3]);
            }
        }
    }

    // ---- store ----
    {
        float* og = out + (size_t)row_start * OUT_DIM + n0;
        const int r0s = wm * 64 + (lane >> 2);
        const int c0s = wn * 64 + 2 * (lane & 3);
        #pragma unroll
        for (int mf = 0; mf < 4; mf++) {
            const int r1 = r0s + mf * 16;
            #pragma unroll
            for (int nf = 0; nf < 8; nf++) {
                const int cc = c0s + nf * 8;
                if (r1 < m_len)
                    *reinterpret_cast<float2*>(og + (size_t)r1 * OUT_DIM + cc) =
                        make_float2(acc[mf][nf][0], acc[mf][nf][1]);
                if (r1 + 8 < m_len)
                    *reinterpret_cast<float2*>(og + (size_t)(r1 + 8) * OUT_DIM + cc) =
                        make_float2(acc[mf][nf][2], acc[mf][nf][3]);
            }
        }
    }
}

extern "C" void kernel_launch(void* const* d_in, const int* in_sizes, int n_in,
                              void* d_out, int out_size) {
    const float* x      = (const float*)d_in[0];
    const int*   msz    = (const int*)  d_in[1];
    const float* w_base = (const float*)d_in[2];
    const float* w_a    = (const float*)d_in[3];
    const float* w_b    = (const float*)d_in[4];
    float*       out    = (float*)d_out;

    static __half* p_xh = nullptr;
    static __half *p_wah, *p_wsh;
    if (!p_xh) {
        cudaGetSymbolAddress((void**)&p_xh,  g_xh);
        cudaGetSymbolAddress((void**)&p_wah, g_wah);
        cudaGetSymbolAddress((void**)&p_wsh, g_wsh);
    }

    const int nx  = (int)((size_t)T_TOK * IN_DIM / 4);
    const int nwa = (int)((size_t)NEXP * IN_DIM * RRANK / 4);
    const int nws = (int)((size_t)NEXP * RRANK * OUT_DIM / 4);
    cvt_kernel<<<8192, 256>>>((const float4*)x,   (uint2*)p_xh,  nx);
    cvt_kernel<<<2048, 256>>>((const float4*)w_a, (uint2*)p_wah, nwa);
    cvt_kernel<<<512,  256>>>((const float4*)w_b, (uint2*)p_wsh, nws);

    static int cfg_done = 0;
    if (!cfg_done) {
        cudaFuncSetAttribute(lora_moe_h4,
                             cudaFuncAttributeMaxDynamicSharedMemorySize, SMEM_BYTES);
        cfg_done = 1;
    }
    dim3 grid(NT, MAX_MTILES);
    lora_moe_h4<<<grid, NTHREADS, SMEM_BYTES>>>(msz, w_base, out);
}